// round 6
// baseline (speedup 1.0000x reference)
#include <cuda_runtime.h>

// Problem constants
#define BB   64
#define KK   4
#define MM   3
#define NPIX 65536            // 256*256
#define NVEC (NPIX / 4)       // 16384 float4 vectors per (b, channel)
#define NVALS 16              // 12 num (k*3+m) + 4 den
#define BLOCKS_PER_B 16
#define THREADS 256
#define NWARPS (THREADS / 32)
#define ITERS 4               // NVEC / (BLOCKS_PER_B*THREADS)
#define GRID (BB * BLOCKS_PER_B)

// Unique per-block partial sums: [block][16]. Plain stores, no zeroing needed.
__device__ float g_part[GRID * NVALS];
__device__ unsigned int g_counter = 0;   // self-resets to 0 every run

__global__ __launch_bounds__(THREADS) void fused_kernel(
    const float* __restrict__ pred,    // [B, K, X, Y]
    const float* __restrict__ inp,     // [B, M, X, Y]
    const int*   __restrict__ heart,   // [B, 1, X, Y]
    const float* __restrict__ mu_data, // [K, M]
    float*       __restrict__ out)     // scalar
{
    const int b   = blockIdx.x / BLOCKS_PER_B;
    const int blk = blockIdx.x % BLOCKS_PER_B;

    const float4* __restrict__ pred4  = (const float4*)pred;
    const float4* __restrict__ inp4   = (const float4*)inp;
    const int4*   __restrict__ heart4 = (const int4*)heart;

    float acc[NVALS];
    #pragma unroll
    for (int i = 0; i < NVALS; i++) acc[i] = 0.0f;

    const int vec_base = blk * (NVEC / BLOCKS_PER_B) + threadIdx.x;

    #pragma unroll
    for (int it = 0; it < ITERS; it++) {
        const int v = vec_base + it * THREADS;

        // ---- issue ALL 8 loads up front (independent, batched) ----
        const int4   h   = heart4[(long)b * NVEC + v];
        float4 iv[MM];
        #pragma unroll
        for (int m = 0; m < MM; m++)
            iv[m] = inp4[((long)b * MM + m) * NVEC + v];
        float4 p[KK];
        #pragma unroll
        for (int k = 0; k < KK; k++)
            p[k] = pred4[((long)b * KK + k) * NVEC + v];

        // ---- then compute ----
        const float m0 = (h.x == 1) ? 1.0f : 0.0f;
        const float m1 = (h.y == 1) ? 1.0f : 0.0f;
        const float m2 = (h.z == 1) ? 1.0f : 0.0f;
        const float m3 = (h.w == 1) ? 1.0f : 0.0f;

        #pragma unroll
        for (int k = 0; k < KK; k++) {
            const float p0 = p[k].x * m0, p1 = p[k].y * m1;
            const float p2 = p[k].z * m2, p3 = p[k].w * m3;
            acc[12 + k] += (p0 + p1) + (p2 + p3);
            #pragma unroll
            for (int m = 0; m < MM; m++) {
                acc[k * MM + m] = fmaf(p0, iv[m].x,
                                  fmaf(p1, iv[m].y,
                                  fmaf(p2, iv[m].z,
                                  fmaf(p3, iv[m].w, acc[k * MM + m]))));
            }
        }
    }

    // Warp reduction of all 16 accumulators
    #pragma unroll
    for (int i = 0; i < NVALS; i++) {
        float v = acc[i];
        #pragma unroll
        for (int o = 16; o > 0; o >>= 1)
            v += __shfl_down_sync(0xffffffffu, v, o);
        acc[i] = v;
    }

    // Cross-warp: plain STS per warp, then 16-thread gather (no smem atomics)
    __shared__ float s_part[NWARPS][NVALS];
    __shared__ bool  s_is_last;
    const int lane = threadIdx.x & 31;
    const int wid  = threadIdx.x >> 5;
    if (lane == 0) {
        #pragma unroll
        for (int i = 0; i < NVALS; i++)
            s_part[wid][i] = acc[i];
    }
    __syncthreads();
    if (threadIdx.x < NVALS) {
        float s = 0.0f;
        #pragma unroll
        for (int w = 0; w < NWARPS; w++)
            s += s_part[w][threadIdx.x];
        g_part[blockIdx.x * NVALS + threadIdx.x] = s;
    }

    // Last-block-done detection
    __threadfence();
    if (threadIdx.x == 0) {
        unsigned int old = atomicAdd(&g_counter, 1u);
        s_is_last = (old == (unsigned)(GRID - 1));
    }
    __syncthreads();
    if (!s_is_last) return;

    // ---- finalize (one block; partials are L2-resident) ----
    __shared__ float s_sum[BB][NVALS];   // 4 KB
    for (int idx = threadIdx.x; idx < BB * NVALS; idx += THREADS) {
        const int bb = idx / NVALS, j = idx % NVALS;
        float s = 0.0f;
        #pragma unroll
        for (int p2 = 0; p2 < BLOCKS_PER_B; p2++)
            s += g_part[(bb * BLOCKS_PER_B + p2) * NVALS + j];
        s_sum[bb][j] = s;
    }
    __syncthreads();

    float v = 0.0f;
    if (threadIdx.x < KK * MM) {
        const int k = threadIdx.x / MM, m = threadIdx.x % MM;
        float s = 0.0f;
        for (int bb = 0; bb < BB; bb++) {
            const float den = s_sum[bb][12 + k] + 1e-10f;
            s += s_sum[bb][k * MM + m] / den;
        }
        const float mu_mean = s * (1.0f / (float)BB);
        const float d = mu_data[k * MM + m] - mu_mean;
        v = d * d;
    }
    if (threadIdx.x < 32) {
        #pragma unroll
        for (int o = 16; o > 0; o >>= 1)
            v += __shfl_down_sync(0xffffffffu, v, o);
        if (threadIdx.x == 0) {
            out[0] = v;
            g_counter = 0;   // reset for next (graph-replayed) run
        }
    }
}

extern "C" void kernel_launch(void* const* d_in, const int* in_sizes, int n_in,
                              void* d_out, int out_size)
{
    const float* pred    = (const float*)d_in[0];
    const float* inp     = (const float*)d_in[1];
    const int*   heart   = (const int*)d_in[2];
    const float* mu_data = (const float*)d_in[3];
    float* out = (float*)d_out;

    fused_kernel<<<GRID, THREADS>>>(pred, inp, heart, mu_data, out);
}

// round 7
// speedup vs baseline: 1.1098x; 1.1098x over previous
#include <cuda_runtime.h>
#include <cstdint>

// Problem constants
#define BB   64
#define KK   4
#define MM   3
#define NPIX 65536            // 256*256
#define NVEC (NPIX / 4)       // 16384 float4 vectors per (b, channel)
#define NVALS 16              // 12 num (k*3+m) + 4 den
#define BLOCKS_PER_B 16
#define THREADS 256
#define NWARPS (THREADS / 32)
#define GRID (BB * BLOCKS_PER_B)

#define CHUNK_VECS   (NVEC / BLOCKS_PER_B)   // 1024 float4 vecs per block per channel
#define STAGE_VECS   256                     // one vec per thread per stage
#define NSTAGE_ITERS (CHUNK_VECS / STAGE_VECS)  // 4
#define SEG_BYTES    (STAGE_VECS * 16)       // 4096 bytes per channel segment
#define NSEG         8                       // 4 pred + 3 inp + 1 heart
#define STAGE_BYTES  (NSEG * SEG_BYTES)      // 32768
#define NSTAGES      2
#define DATA_OFF     1024                    // smem data offset (mbarriers below)
#define DYN_SMEM     (DATA_OFF + NSTAGES * STAGE_BYTES)   // 66560

__device__ float g_part[GRID * NVALS];
__device__ unsigned int g_counter = 0;

__device__ __forceinline__ uint32_t smem_u32(const void* p) {
    uint32_t a;
    asm("{ .reg .u64 t; cvta.to.shared.u64 t, %1; cvt.u32.u64 %0, t; }"
        : "=r"(a) : "l"(p));
    return a;
}

__device__ __forceinline__ void mbar_init(uint32_t mbar, uint32_t count) {
    asm volatile("mbarrier.init.shared.b64 [%0], %1;" :: "r"(mbar), "r"(count) : "memory");
}

__device__ __forceinline__ void mbar_expect_tx(uint32_t mbar, uint32_t bytes) {
    asm volatile("mbarrier.arrive.expect_tx.shared.b64 _, [%0], %1;"
                 :: "r"(mbar), "r"(bytes) : "memory");
}

__device__ __forceinline__ void mbar_wait(uint32_t mbar, uint32_t parity) {
    asm volatile(
        "{\n\t"
        ".reg .pred p;\n\t"
        "WAIT_%=:\n\t"
        "mbarrier.try_wait.parity.acquire.cta.shared::cta.b64 p, [%0], %1, 0x989680;\n\t"
        "@!p bra WAIT_%=;\n\t"
        "}"
        :: "r"(mbar), "r"(parity) : "memory");
}

__device__ __forceinline__ void bulk_g2s(uint32_t dst, const void* src,
                                         uint32_t bytes, uint32_t mbar) {
    asm volatile(
        "cp.async.bulk.shared::cluster.global.mbarrier::complete_tx::bytes "
        "[%0], [%1], %2, [%3];"
        :: "r"(dst), "l"(src), "r"(bytes), "r"(mbar) : "memory");
}

__global__ __launch_bounds__(THREADS) void fused_kernel(
    const float* __restrict__ pred,    // [B, K, X, Y]
    const float* __restrict__ inp,     // [B, M, X, Y]
    const int*   __restrict__ heart,   // [B, 1, X, Y]
    const float* __restrict__ mu_data, // [K, M]
    float*       __restrict__ out)     // scalar
{
    extern __shared__ char smem[];
    const uint32_t smem_base = smem_u32(smem);
    const int tid = threadIdx.x;
    const int b   = blockIdx.x / BLOCKS_PER_B;
    const int blk = blockIdx.x % BLOCKS_PER_B;
    const long chunk_base = (long)blk * CHUNK_VECS;   // vec offset within channel

    const float4* __restrict__ pred4  = (const float4*)pred;
    const float4* __restrict__ inp4   = (const float4*)inp;
    const int4*   __restrict__ heart4 = (const int4*)heart;

    // mbarriers: full[s] at smem_base + s*8, count=1 (expect_tx arrive)
    if (tid == 0) {
        mbar_init(smem_base + 0, 1);
        mbar_init(smem_base + 8, 1);
    }
    __syncthreads();

    // Issue a stage: 8 bulk copies of SEG_BYTES each
    auto issue_stage = [&](int it) {
        const int stage = it & 1;
        const uint32_t sb = smem_base + DATA_OFF + stage * STAGE_BYTES;
        const uint32_t mbar = smem_base + stage * 8;
        const long v0 = chunk_base + (long)it * STAGE_VECS;
        mbar_expect_tx(mbar, STAGE_BYTES);
        #pragma unroll
        for (int k = 0; k < KK; k++)
            bulk_g2s(sb + k * SEG_BYTES,
                     pred4 + ((long)b * KK + k) * NVEC + v0, SEG_BYTES, mbar);
        #pragma unroll
        for (int m = 0; m < MM; m++)
            bulk_g2s(sb + (4 + m) * SEG_BYTES,
                     inp4 + ((long)b * MM + m) * NVEC + v0, SEG_BYTES, mbar);
        bulk_g2s(sb + 7 * SEG_BYTES,
                 heart4 + (long)b * NVEC + v0, SEG_BYTES, mbar);
    };

    // Prologue: fill both stages
    if (tid == 0) {
        issue_stage(0);
        issue_stage(1);
    }

    float acc[NVALS];
    #pragma unroll
    for (int i = 0; i < NVALS; i++) acc[i] = 0.0f;

    for (int it = 0; it < NSTAGE_ITERS; it++) {
        const int stage = it & 1;
        const uint32_t sb = smem_base + DATA_OFF + stage * STAGE_BYTES;
        mbar_wait(smem_base + stage * 8, (it >> 1) & 1);

        // Consume: thread t owns vec t of this stage (LDS.128, conflict-free)
        const char* sp = smem + (sb - smem_base);
        const int4 h = *(const int4*)(sp + 7 * SEG_BYTES + tid * 16);
        const float m0 = (h.x == 1) ? 1.0f : 0.0f;
        const float m1 = (h.y == 1) ? 1.0f : 0.0f;
        const float m2 = (h.z == 1) ? 1.0f : 0.0f;
        const float m3 = (h.w == 1) ? 1.0f : 0.0f;

        float4 iv[MM];
        #pragma unroll
        for (int m = 0; m < MM; m++)
            iv[m] = *(const float4*)(sp + (4 + m) * SEG_BYTES + tid * 16);

        #pragma unroll
        for (int k = 0; k < KK; k++) {
            const float4 p = *(const float4*)(sp + k * SEG_BYTES + tid * 16);
            const float p0 = p.x * m0, p1 = p.y * m1;
            const float p2 = p.z * m2, p3 = p.w * m3;
            acc[12 + k] += (p0 + p1) + (p2 + p3);
            #pragma unroll
            for (int m = 0; m < MM; m++) {
                acc[k * MM + m] = fmaf(p0, iv[m].x,
                                  fmaf(p1, iv[m].y,
                                  fmaf(p2, iv[m].z,
                                  fmaf(p3, iv[m].w, acc[k * MM + m]))));
            }
        }

        __syncthreads();   // all threads done with this stage
        if (tid == 0 && it + 2 < NSTAGE_ITERS)
            issue_stage(it + 2);
    }

    // Warp reduction of all 16 accumulators
    #pragma unroll
    for (int i = 0; i < NVALS; i++) {
        float v = acc[i];
        #pragma unroll
        for (int o = 16; o > 0; o >>= 1)
            v += __shfl_down_sync(0xffffffffu, v, o);
        acc[i] = v;
    }

    // Cross-warp: plain STS per warp, then 16-thread gather
    __shared__ float s_part[NWARPS][NVALS];
    __shared__ bool  s_is_last;
    const int lane = tid & 31;
    const int wid  = tid >> 5;
    if (lane == 0) {
        #pragma unroll
        for (int i = 0; i < NVALS; i++)
            s_part[wid][i] = acc[i];
    }
    __syncthreads();
    if (tid < NVALS) {
        float s = 0.0f;
        #pragma unroll
        for (int w = 0; w < NWARPS; w++)
            s += s_part[w][tid];
        g_part[blockIdx.x * NVALS + tid] = s;
    }

    // Last-block-done detection
    __threadfence();
    if (tid == 0) {
        unsigned int old = atomicAdd(&g_counter, 1u);
        s_is_last = (old == (unsigned)(GRID - 1));
    }
    __syncthreads();
    if (!s_is_last) return;

    // ---- finalize (one block; partials are L2-resident) ----
    __shared__ float s_sum[BB][NVALS];
    for (int idx = tid; idx < BB * NVALS; idx += THREADS) {
        const int bb = idx / NVALS, j = idx % NVALS;
        float s = 0.0f;
        #pragma unroll
        for (int p2 = 0; p2 < BLOCKS_PER_B; p2++)
            s += g_part[(bb * BLOCKS_PER_B + p2) * NVALS + j];
        s_sum[bb][j] = s;
    }
    __syncthreads();

    float v = 0.0f;
    if (tid < KK * MM) {
        const int k = tid / MM, m = tid % MM;
        float s = 0.0f;
        for (int bb = 0; bb < BB; bb++) {
            const float den = s_sum[bb][12 + k] + 1e-10f;
            s += s_sum[bb][k * MM + m] / den;
        }
        const float mu_mean = s * (1.0f / (float)BB);
        const float d = mu_data[k * MM + m] - mu_mean;
        v = d * d;
    }
    if (tid < 32) {
        #pragma unroll
        for (int o = 16; o > 0; o >>= 1)
            v += __shfl_down_sync(0xffffffffu, v, o);
        if (tid == 0) {
            out[0] = v;
            g_counter = 0;   // reset for next (graph-replayed) run
        }
    }
}

extern "C" void kernel_launch(void* const* d_in, const int* in_sizes, int n_in,
                              void* d_out, int out_size)
{
    const float* pred    = (const float*)d_in[0];
    const float* inp     = (const float*)d_in[1];
    const int*   heart   = (const int*)d_in[2];
    const float* mu_data = (const float*)d_in[3];
    float* out = (float*)d_out;

    cudaFuncSetAttribute(fused_kernel,
                         cudaFuncAttributeMaxDynamicSharedMemorySize, DYN_SMEM);
    fused_kernel<<<GRID, THREADS, DYN_SMEM>>>(pred, inp, heart, mu_data, out);
}